// round 4
// baseline (speedup 1.0000x reference)
#include <cuda_runtime.h>

#define NQ 16384
#define NS 4096
#define NP 16
#define D2C 256
#define CIN 512
#define COUT 256
#define BIGD 1e8f
#define WEPS 1e-8f
#define BNEPS 1e-5f

// ---------------- scratch (static device globals; no allocation) -------------
__device__ __align__(16) float g_feats[NQ * CIN];   // [N][512] row-major
__device__ __align__(16) float g_f2t[NS * D2C];     // points2 transposed [S][256]
__device__ __align__(16) float g_y[NQ * COUT];      // pre-BN layer1
__device__ __align__(16) float g_x1[NQ * COUT];     // post layer1
__device__ __align__(16) float g_y2[NQ * COUT];     // pre-BN layer2
__device__ int   g_kidx[NQ * 3];
__device__ float g_kw[NQ * 3];
__device__ __align__(16) float4 g_b2[NS];           // bucketed xyz2 (x,y,z,origIdx)
__device__ __align__(16) float4 g_b1[NQ];           // bucketed xyz1 (x,y,z,origN)
__device__ int g_qp[NQ];                            // piece id per bucketed query
__device__ int g_cnt1[NP], g_cnt2[NP], g_fill1[NP], g_fill2[NP];
__device__ int g_off1[NP + 1], g_off2[NP + 1];
__device__ int g_is64;
__device__ float g_ps[64 * COUT], g_pq[64 * COUT];  // BN partial sums (deterministic)
__device__ float g_scale[COUT], g_shift[COUT];

// piece ids may arrive as int32 or int64 depending on JAX x64 config; detect.
__device__ __forceinline__ int get_pid(const int* w, int i) {
    return g_is64 ? w[2 * i] : w[i];
}

// ---------------- init + dtype detection ------------------------------------
__global__ void k_init(const int* pid1w) {
    int t = threadIdx.x;  // 256 threads
    if (t < NP) { g_cnt1[t] = 0; g_cnt2[t] = 0; g_fill1[t] = 0; g_fill2[t] = 0; }
    __shared__ int nz;
    if (t == 0) nz = 0;
    __syncthreads();
    // If int64, high word of first 256 elements are all zero (values in [0,16)).
    if (pid1w[2 * t + 1] != 0) atomicOr(&nz, 1);
    __syncthreads();
    if (t == 0) g_is64 = (nz == 0) ? 1 : 0;
}

__global__ void k_count(const int* pid1, const int* pid2) {
    int i = blockIdx.x * blockDim.x + threadIdx.x;
    if (i < NS) atomicAdd(&g_cnt2[get_pid(pid2, i)], 1);
    if (i < NQ) atomicAdd(&g_cnt1[get_pid(pid1, i)], 1);
}

__global__ void k_offsets() {
    int s1 = 0, s2 = 0;
    g_off1[0] = 0; g_off2[0] = 0;
    for (int p = 0; p < NP; p++) {
        s1 += g_cnt1[p]; g_off1[p + 1] = s1;
        s2 += g_cnt2[p]; g_off2[p + 1] = s2;
    }
}

__global__ void k_scatter(const float* __restrict__ x1, const float* __restrict__ x2,
                          const int* __restrict__ pid1, const int* __restrict__ pid2) {
    int i = blockIdx.x * blockDim.x + threadIdx.x;
    if (i < NS) {
        int p = get_pid(pid2, i);
        int pos = g_off2[p] + atomicAdd(&g_fill2[p], 1);
        g_b2[pos] = make_float4(x2[i], x2[NS + i], x2[2 * NS + i], __int_as_float(i));
    }
    if (i < NQ) {
        int p = get_pid(pid1, i);
        int pos = g_off1[p] + atomicAdd(&g_fill1[p], 1);
        g_b1[pos] = make_float4(x1[i], x1[NQ + i], x1[2 * NQ + i], __int_as_float(i));
        g_qp[pos] = p;
    }
}

// ---------------- generic 32x32 shared-tile transpose ------------------------
// dst[col*dstStride + row] = src[row*Cc + col]
__global__ void k_transpose(const float* __restrict__ src, float* __restrict__ dst,
                            int Cc, int dstStride) {
    __shared__ float tile[32][33];
    int c0 = blockIdx.x * 32, r0 = blockIdx.y * 32;
    int tx = threadIdx.x, ty = threadIdx.y;
#pragma unroll
    for (int i = 0; i < 4; i++)
        tile[ty + 8 * i][tx] = src[(r0 + ty + 8 * i) * Cc + c0 + tx];
    __syncthreads();
#pragma unroll
    for (int i = 0; i < 4; i++)
        dst[(c0 + ty + 8 * i) * (long)dstStride + r0 + tx] = tile[tx][ty + 8 * i];
}

// ---------------- KNN (top-3 within same piece) ------------------------------
__device__ __forceinline__ void topk_ins(float d, int i,
                                         float& d0, float& d1, float& d2,
                                         int& i0, int& i1, int& i2) {
    if (d < d2) {
        if (d < d1) {
            d2 = d1; i2 = i1;
            if (d < d0) { d1 = d0; i1 = i0; d0 = d; i0 = i; }
            else        { d1 = d;  i1 = i; }
        } else { d2 = d; i2 = i; }
    }
}

__global__ void k_knn() {
    int t = blockIdx.x * blockDim.x + threadIdx.x;
    int q = t >> 2;
    int l4 = t & 3;
    float4 Q = g_b1[q];
    int p = g_qp[q];
    int s0 = g_off2[p], s1 = g_off2[p + 1];
    const float FINF = __int_as_float(0x7f800000);
    float d0 = FINF, d1 = FINF, d2 = FINF;
    int i0 = 0, i1 = 0, i2 = 0;
    for (int j = s0 + l4; j < s1; j += 4) {
        float4 T = g_b2[j];
        float dx = Q.x - T.x, dy = Q.y - T.y, dz = Q.z - T.z;
        float d = fmaf(dx, dx, fmaf(dy, dy, dz * dz));
        topk_ins(d, __float_as_int(T.w), d0, d1, d2, i0, i1, i2);
    }
    // butterfly merge across the 4 lanes of this query
#pragma unroll
    for (int m = 1; m <= 2; m <<= 1) {
        float e0 = __shfl_xor_sync(0xffffffffu, d0, m);
        float e1 = __shfl_xor_sync(0xffffffffu, d1, m);
        float e2 = __shfl_xor_sync(0xffffffffu, d2, m);
        int j0 = __shfl_xor_sync(0xffffffffu, i0, m);
        int j1 = __shfl_xor_sync(0xffffffffu, i1, m);
        int j2 = __shfl_xor_sync(0xffffffffu, i2, m);
        topk_ins(e0, j0, d0, d1, d2, i0, i1, i2);
        topk_ins(e1, j1, d0, d1, d2, i0, i1, i2);
        topk_ins(e2, j2, d0, d1, d2, i0, i1, i2);
    }
    if (l4 == 0) {
        int n = __float_as_int(Q.w);
        // reference fill semantics: invalid slots -> idx[:,0], distance BIG
        if (!(d0 < FINF)) { i0 = 0;  d0 = BIGD; }
        if (!(d1 < FINF)) { i1 = i0; d1 = BIGD; }
        if (!(d2 < FINF)) { i2 = i0; d2 = BIGD; }
        float w0 = 1.0f / (d0 + WEPS);
        float w1 = 1.0f / (d1 + WEPS);
        float w2 = 1.0f / (d2 + WEPS);
        float inv = 1.0f / (w0 + w1 + w2);
        g_kidx[n * 3 + 0] = i0; g_kidx[n * 3 + 1] = i1; g_kidx[n * 3 + 2] = i2;
        g_kw[n * 3 + 0] = w0 * inv; g_kw[n * 3 + 1] = w1 * inv; g_kw[n * 3 + 2] = w2 * inv;
    }
}

// ---------------- interpolation: feats[n][256+c] = sum_k w_k * f2t[idx_k][c] -
__global__ void k_interp() {
    int wi = (blockIdx.x * blockDim.x + threadIdx.x) >> 5;
    int lane = threadIdx.x & 31;
    if (wi >= NQ) return;
    int i0 = g_kidx[wi * 3 + 0], i1 = g_kidx[wi * 3 + 1], i2 = g_kidx[wi * 3 + 2];
    float w0 = g_kw[wi * 3 + 0], w1 = g_kw[wi * 3 + 1], w2 = g_kw[wi * 3 + 2];
    const float4* r0 = (const float4*)(g_f2t + (long)i0 * D2C);
    const float4* r1 = (const float4*)(g_f2t + (long)i1 * D2C);
    const float4* r2 = (const float4*)(g_f2t + (long)i2 * D2C);
    float4* o = (float4*)(g_feats + (long)wi * CIN + 256);
#pragma unroll
    for (int c = lane; c < D2C / 4; c += 32) {
        float4 a = r0[c], b = r1[c], cc = r2[c];
        float4 v;
        v.x = w0 * a.x + w1 * b.x + w2 * cc.x;
        v.y = w0 * a.y + w1 * b.y + w2 * cc.y;
        v.z = w0 * a.z + w1 * b.z + w2 * cc.z;
        v.w = w0 * a.w + w1 * b.w + w2 * cc.w;
        o[c] = v;
    }
}

// ---------------- SGEMM: C[i][j] = sum_k A[i][k]*B[j][k]  (TN, K-major) -------
// A: [16384][K], B: [256][K], C: [16384][256].  128x128x16 tiles, 8x8 micro.
__global__ __launch_bounds__(256) void k_gemm(const float* __restrict__ A,
                                              const float* __restrict__ B,
                                              float* __restrict__ C, int K) {
    __shared__ float As[16][132];
    __shared__ float Bs[16][132];
    int i0 = blockIdx.x * 128;
    int j0 = blockIdx.y * 128;
    int tid = threadIdx.x;
    int r = tid >> 2;
    int kq = (tid & 3) << 2;
    int ty = tid >> 4, tx = tid & 15;
    float acc[8][8] = {};
    for (int k0 = 0; k0 < K; k0 += 16) {
        float4 a0 = *(const float4*)&A[(long)(i0 + r) * K + k0 + kq];
        float4 a1 = *(const float4*)&A[(long)(i0 + r + 64) * K + k0 + kq];
        float4 b0 = *(const float4*)&B[(long)(j0 + r) * K + k0 + kq];
        float4 b1 = *(const float4*)&B[(long)(j0 + r + 64) * K + k0 + kq];
        __syncthreads();
        As[kq + 0][r] = a0.x; As[kq + 1][r] = a0.y; As[kq + 2][r] = a0.z; As[kq + 3][r] = a0.w;
        As[kq + 0][r + 64] = a1.x; As[kq + 1][r + 64] = a1.y; As[kq + 2][r + 64] = a1.z; As[kq + 3][r + 64] = a1.w;
        Bs[kq + 0][r] = b0.x; Bs[kq + 1][r] = b0.y; Bs[kq + 2][r] = b0.z; Bs[kq + 3][r] = b0.w;
        Bs[kq + 0][r + 64] = b1.x; Bs[kq + 1][r + 64] = b1.y; Bs[kq + 2][r + 64] = b1.z; Bs[kq + 3][r + 64] = b1.w;
        __syncthreads();
#pragma unroll
        for (int kk = 0; kk < 16; kk++) {
            float a[8], b[8];
            *(float4*)(a)     = *(const float4*)&As[kk][ty * 8];
            *(float4*)(a + 4) = *(const float4*)&As[kk][ty * 8 + 4];
            *(float4*)(b)     = *(const float4*)&Bs[kk][tx * 8];
            *(float4*)(b + 4) = *(const float4*)&Bs[kk][tx * 8 + 4];
#pragma unroll
            for (int ii = 0; ii < 8; ii++)
#pragma unroll
                for (int jj = 0; jj < 8; jj++)
                    acc[ii][jj] = fmaf(a[ii], b[jj], acc[ii][jj]);
        }
    }
#pragma unroll
    for (int ii = 0; ii < 8; ii++) {
        float4 o1 = make_float4(acc[ii][0], acc[ii][1], acc[ii][2], acc[ii][3]);
        float4 o2 = make_float4(acc[ii][4], acc[ii][5], acc[ii][6], acc[ii][7]);
        long row = (long)(i0 + ty * 8 + ii) * COUT + j0 + tx * 8;
        *(float4*)&C[row] = o1;
        *(float4*)&C[row + 4] = o2;
    }
}

// ---------------- BN stats (deterministic partials) --------------------------
__global__ void k_bnstats(const float* __restrict__ Y) {
    int t = threadIdx.x;     // channel j
    int b = blockIdx.x;      // row chunk
    const float* base = Y + (long)b * 256 * COUT + t;
    float s = 0.f, q = 0.f;
#pragma unroll 8
    for (int i = 0; i < 256; i++) {
        float v = base[(long)i * COUT];
        s += v;
        q = fmaf(v, v, q);
    }
    g_ps[b * COUT + t] = s;
    g_pq[b * COUT + t] = q;
}

__global__ void k_bnfinal(const float* __restrict__ g, const float* __restrict__ bt) {
    int j = threadIdx.x;
    float s = 0.f, q = 0.f;
    for (int b = 0; b < 64; b++) { s += g_ps[b * COUT + j]; q += g_pq[b * COUT + j]; }
    float mean = s * (1.0f / NQ);
    float var = q * (1.0f / NQ) - mean * mean;
    float rstd = rsqrtf(var + BNEPS);
    float sc = g[j] * rstd;
    g_scale[j] = sc;
    g_shift[j] = bt[j] - mean * sc;
}

__global__ void k_normrelu(const float* __restrict__ Y, float* __restrict__ X) {
    int i4 = blockIdx.x * blockDim.x + threadIdx.x;   // float4 index
    float4 v = ((const float4*)Y)[i4];
    int j = (i4 * 4) & (COUT - 1);
    float4 sc = *(const float4*)&g_scale[j];
    float4 sh = *(const float4*)&g_shift[j];
    float4 o;
    o.x = fmaxf(fmaf(v.x, sc.x, sh.x), 0.f);
    o.y = fmaxf(fmaf(v.y, sc.y, sh.y), 0.f);
    o.z = fmaxf(fmaf(v.z, sc.z, sh.z), 0.f);
    o.w = fmaxf(fmaf(v.w, sc.w, sh.w), 0.f);
    ((float4*)X)[i4] = o;
}

// final: out[o*N + n] = relu(norm(y2[n][o]))  — transposing write via smem tile
__global__ void k_outtrans(const float* __restrict__ Y, float* __restrict__ out) {
    __shared__ float tile[32][33];
    int n0 = blockIdx.x * 32, o0 = blockIdx.y * 32;
    int tx = threadIdx.x, ty = threadIdx.y;
#pragma unroll
    for (int i = 0; i < 4; i++)
        tile[ty + 8 * i][tx] = Y[(long)(n0 + ty + 8 * i) * COUT + o0 + tx];
    __syncthreads();
#pragma unroll
    for (int i = 0; i < 4; i++) {
        int o = o0 + ty + 8 * i;
        float v = fmaf(tile[tx][ty + 8 * i], g_scale[o], g_shift[o]);
        out[(long)o * NQ + n0 + tx] = fmaxf(v, 0.f);
    }
}

// ---------------- launch ------------------------------------------------------
extern "C" void kernel_launch(void* const* d_in, const int* in_sizes, int n_in,
                              void* d_out, int out_size) {
    const float* xyz1 = (const float*)d_in[0];
    const float* xyz2 = (const float*)d_in[1];
    const int* pid1 = (const int*)d_in[2];
    const int* pid2 = (const int*)d_in[3];
    const float* points1 = (const float*)d_in[4];
    const float* points2 = (const float*)d_in[5];
    const float* w0 = (const float*)d_in[6];
    const float* gg0 = (const float*)d_in[8];
    const float* bt0 = (const float*)d_in[9];
    const float* w1 = (const float*)d_in[10];
    const float* gg1 = (const float*)d_in[12];
    const float* bt1 = (const float*)d_in[13];
    float* out = (float*)d_out;

    float *p_feats, *p_f2t, *p_y, *p_x1, *p_y2;
    cudaGetSymbolAddress((void**)&p_feats, g_feats);
    cudaGetSymbolAddress((void**)&p_f2t, g_f2t);
    cudaGetSymbolAddress((void**)&p_y, g_y);
    cudaGetSymbolAddress((void**)&p_x1, g_x1);
    cudaGetSymbolAddress((void**)&p_y2, g_y2);

    k_init<<<1, 256>>>(pid1);
    k_count<<<NQ / 256, 256>>>(pid1, pid2);
    k_offsets<<<1, 1>>>();
    k_scatter<<<NQ / 256, 256>>>(xyz1, xyz2, pid1, pid2);

    // points1 [256][N] -> feats[n][c] (c<256); points2 [256][S] -> f2t[s][c]
    k_transpose<<<dim3(NQ / 32, 256 / 32), dim3(32, 8)>>>(points1, p_feats, NQ, CIN);
    k_transpose<<<dim3(NS / 32, 256 / 32), dim3(32, 8)>>>(points2, p_f2t, NS, D2C);

    k_knn<<<(NQ * 4) / 256, 256>>>();
    k_interp<<<(NQ * 32) / 256, 256>>>();

    // layer 1: 512 -> 256  (bias skipped: exactly cancels through batch-norm)
    k_gemm<<<dim3(NQ / 128, 2), 256>>>(p_feats, w0, p_y, CIN);
    k_bnstats<<<64, 256>>>(p_y);
    k_bnfinal<<<1, 256>>>(gg0, bt0);
    k_normrelu<<<(NQ * COUT / 4) / 256, 256>>>(p_y, p_x1);

    // layer 2: 256 -> 256
    k_gemm<<<dim3(NQ / 128, 2), 256>>>(p_x1, w1, p_y2, COUT);
    k_bnstats<<<64, 256>>>(p_y2);
    k_bnfinal<<<1, 256>>>(gg1, bt1);
    k_outtrans<<<dim3(NQ / 32, COUT / 32), dim3(32, 8)>>>(p_y2, out);
}

// round 6
// speedup vs baseline: 1.2168x; 1.2168x over previous
#include <cuda_runtime.h>
#include <cuda_bf16.h>
#include <cstdint>

#define NQ 16384
#define NS 4096
#define NP 16
#define D2C 256
#define CIN 512
#define COUT 256
#define BIGD 1e8f
#define WEPS 1e-8f
#define BNEPS 1e-5f

// ---------------- scratch (static device globals; no allocation) -------------
__device__ __align__(16) float g_feats[NQ * CIN];   // [N][512] row-major
__device__ __align__(16) float g_f2t[NS * D2C];     // points2 transposed [S][256]
__device__ __align__(16) float g_y[NQ * COUT];      // pre-BN layer1
__device__ __align__(16) float g_y2[NQ * COUT];     // pre-BN layer2
__device__ int   g_kidx[NQ * 3];
__device__ float g_kw[NQ * 3];
__device__ __align__(16) float4 g_b2[NS];           // bucketed xyz2 (x,y,z,origIdx)
__device__ __align__(16) float4 g_b1[NQ];           // bucketed xyz1 (x,y,z,origN)
__device__ int g_qp[NQ];                            // piece id per bucketed query
__device__ int g_cnt1[NP], g_cnt2[NP], g_fill1[NP], g_fill2[NP];
__device__ int g_off1[NP + 1], g_off2[NP + 1];
__device__ int g_is64;
__device__ float g_ps[128 * COUT], g_pq[128 * COUT]; // BN partials (per GEMM CTA)
__device__ float g_scale[COUT], g_shift[COUT];

// piece ids may arrive as int32 or int64 depending on JAX x64 config; detect.
__device__ __forceinline__ int get_pid(const int* w, int i) {
    return g_is64 ? w[2 * i] : w[i];
}

// ---------------- init + dtype detection ------------------------------------
__global__ void k_init(const int* pid1w) {
    int t = threadIdx.x;  // 256 threads
    if (t < NP) { g_cnt1[t] = 0; g_cnt2[t] = 0; g_fill1[t] = 0; g_fill2[t] = 0; }
    __shared__ int nz;
    if (t == 0) nz = 0;
    __syncthreads();
    if (pid1w[2 * t + 1] != 0) atomicOr(&nz, 1);
    __syncthreads();
    if (t == 0) g_is64 = (nz == 0) ? 1 : 0;
}

__global__ void k_count(const int* pid1, const int* pid2) {
    int i = blockIdx.x * blockDim.x + threadIdx.x;
    if (i < NS) atomicAdd(&g_cnt2[get_pid(pid2, i)], 1);
    if (i < NQ) atomicAdd(&g_cnt1[get_pid(pid1, i)], 1);
}

__global__ void k_offsets() {
    int s1 = 0, s2 = 0;
    g_off1[0] = 0; g_off2[0] = 0;
    for (int p = 0; p < NP; p++) {
        s1 += g_cnt1[p]; g_off1[p + 1] = s1;
        s2 += g_cnt2[p]; g_off2[p + 1] = s2;
    }
}

__global__ void k_scatter(const float* __restrict__ x1, const float* __restrict__ x2,
                          const int* __restrict__ pid1, const int* __restrict__ pid2) {
    int i = blockIdx.x * blockDim.x + threadIdx.x;
    if (i < NS) {
        int p = get_pid(pid2, i);
        int pos = g_off2[p] + atomicAdd(&g_fill2[p], 1);
        g_b2[pos] = make_float4(x2[i], x2[NS + i], x2[2 * NS + i], __int_as_float(i));
    }
    if (i < NQ) {
        int p = get_pid(pid1, i);
        int pos = g_off1[p] + atomicAdd(&g_fill1[p], 1);
        g_b1[pos] = make_float4(x1[i], x1[NQ + i], x1[2 * NQ + i], __int_as_float(i));
        g_qp[pos] = p;
    }
}

// ---------------- generic 32x32 shared-tile transpose ------------------------
__global__ void k_transpose(const float* __restrict__ src, float* __restrict__ dst,
                            int Cc, int dstStride) {
    __shared__ float tile[32][33];
    int c0 = blockIdx.x * 32, r0 = blockIdx.y * 32;
    int tx = threadIdx.x, ty = threadIdx.y;
#pragma unroll
    for (int i = 0; i < 4; i++)
        tile[ty + 8 * i][tx] = src[(r0 + ty + 8 * i) * Cc + c0 + tx];
    __syncthreads();
#pragma unroll
    for (int i = 0; i < 4; i++)
        dst[(c0 + ty + 8 * i) * (long)dstStride + r0 + tx] = tile[tx][ty + 8 * i];
}

// ---------------- KNN (top-3 within same piece) ------------------------------
__device__ __forceinline__ void topk_ins(float d, int i,
                                         float& d0, float& d1, float& d2,
                                         int& i0, int& i1, int& i2) {
    if (d < d2) {
        if (d < d1) {
            d2 = d1; i2 = i1;
            if (d < d0) { d1 = d0; i1 = i0; d0 = d; i0 = i; }
            else        { d1 = d;  i1 = i; }
        } else { d2 = d; i2 = i; }
    }
}

__global__ void k_knn() {
    int t = blockIdx.x * blockDim.x + threadIdx.x;
    int q = t >> 2;
    int l4 = t & 3;
    float4 Q = g_b1[q];
    int p = g_qp[q];
    int s0 = g_off2[p], s1 = g_off2[p + 1];
    const float FINF = __int_as_float(0x7f800000);
    float d0 = FINF, d1 = FINF, d2 = FINF;
    int i0 = 0, i1 = 0, i2 = 0;
    for (int j = s0 + l4; j < s1; j += 4) {
        float4 T = g_b2[j];
        float dx = Q.x - T.x, dy = Q.y - T.y, dz = Q.z - T.z;
        float d = fmaf(dx, dx, fmaf(dy, dy, dz * dz));
        topk_ins(d, __float_as_int(T.w), d0, d1, d2, i0, i1, i2);
    }
#pragma unroll
    for (int m = 1; m <= 2; m <<= 1) {
        float e0 = __shfl_xor_sync(0xffffffffu, d0, m);
        float e1 = __shfl_xor_sync(0xffffffffu, d1, m);
        float e2 = __shfl_xor_sync(0xffffffffu, d2, m);
        int j0 = __shfl_xor_sync(0xffffffffu, i0, m);
        int j1 = __shfl_xor_sync(0xffffffffu, i1, m);
        int j2 = __shfl_xor_sync(0xffffffffu, i2, m);
        topk_ins(e0, j0, d0, d1, d2, i0, i1, i2);
        topk_ins(e1, j1, d0, d1, d2, i0, i1, i2);
        topk_ins(e2, j2, d0, d1, d2, i0, i1, i2);
    }
    if (l4 == 0) {
        int n = __float_as_int(Q.w);
        if (!(d0 < FINF)) { i0 = 0;  d0 = BIGD; }
        if (!(d1 < FINF)) { i1 = i0; d1 = BIGD; }
        if (!(d2 < FINF)) { i2 = i0; d2 = BIGD; }
        float w0 = 1.0f / (d0 + WEPS);
        float w1 = 1.0f / (d1 + WEPS);
        float w2 = 1.0f / (d2 + WEPS);
        float inv = 1.0f / (w0 + w1 + w2);
        g_kidx[n * 3 + 0] = i0; g_kidx[n * 3 + 1] = i1; g_kidx[n * 3 + 2] = i2;
        g_kw[n * 3 + 0] = w0 * inv; g_kw[n * 3 + 1] = w1 * inv; g_kw[n * 3 + 2] = w2 * inv;
    }
}

// ---------------- interpolation ----------------------------------------------
__global__ void k_interp() {
    int wi = (blockIdx.x * blockDim.x + threadIdx.x) >> 5;
    int lane = threadIdx.x & 31;
    if (wi >= NQ) return;
    int i0 = g_kidx[wi * 3 + 0], i1 = g_kidx[wi * 3 + 1], i2 = g_kidx[wi * 3 + 2];
    float w0 = g_kw[wi * 3 + 0], w1 = g_kw[wi * 3 + 1], w2 = g_kw[wi * 3 + 2];
    const float4* r0 = (const float4*)(g_f2t + (long)i0 * D2C);
    const float4* r1 = (const float4*)(g_f2t + (long)i1 * D2C);
    const float4* r2 = (const float4*)(g_f2t + (long)i2 * D2C);
    float4* o = (float4*)(g_feats + (long)wi * CIN + 256);
#pragma unroll
    for (int c = lane; c < D2C / 4; c += 32) {
        float4 a = r0[c], b = r1[c], cc = r2[c];
        float4 v;
        v.x = w0 * a.x + w1 * b.x + w2 * cc.x;
        v.y = w0 * a.y + w1 * b.y + w2 * cc.y;
        v.z = w0 * a.z + w1 * b.z + w2 * cc.z;
        v.w = w0 * a.w + w1 * b.w + w2 * cc.w;
        o[c] = v;
    }
}

// ============================================================================
// HMMA bf16x3 GEMM: C[i][j] = sum_k A[i][k]*B[j][k]  (TN, K-major, fp32 acc)
// CTA = 128M x 256N, K chunk 32, hi/lo bf16 planes, double buffered.
// Epilogue: store Y + per-CTA BN partial sum/sumsq. Optional BN+ReLU on A load.
// ============================================================================
#define HROW 80                       // smem row pitch (bytes) -> conflict-free ldmatrix
#define HA_SZ (128 * HROW)            // 10240: one A plane
#define HB_SZ (256 * HROW)            // 20480: one B plane
#define HBUF (2 * HA_SZ + 2 * HB_SZ)  // 61440: [Ahi][Alo][Bhi][Blo]
#define HSMEM (2 * HBUF)              // 122880

__device__ __forceinline__ uint32_t smem_u32(const void* p) {
    uint32_t a;
    asm("{ .reg .u64 t; cvta.to.shared.u64 t, %1; cvt.u32.u64 %0, t; }" : "=r"(a) : "l"(p));
    return a;
}
__device__ __forceinline__ void ldsm4(uint32_t* r, uint32_t addr) {
    asm volatile("ldmatrix.sync.aligned.m8n8.x4.shared.b16 {%0,%1,%2,%3}, [%4];"
                 : "=r"(r[0]), "=r"(r[1]), "=r"(r[2]), "=r"(r[3]) : "r"(addr));
}
__device__ __forceinline__ void mma16816(float* c, const uint32_t* a, uint32_t b0, uint32_t b1) {
    asm volatile(
        "mma.sync.aligned.m16n8k16.row.col.f32.bf16.bf16.f32 "
        "{%0,%1,%2,%3}, {%4,%5,%6,%7}, {%8,%9}, {%0,%1,%2,%3};"
        : "+f"(c[0]), "+f"(c[1]), "+f"(c[2]), "+f"(c[3])
        : "r"(a[0]), "r"(a[1]), "r"(a[2]), "r"(a[3]), "r"(b0), "r"(b1));
}
__device__ __forceinline__ uint32_t packbf2(float a, float b) {
    uint32_t ua = (uint32_t)__bfloat16_as_ushort(__float2bfloat16_rn(a));
    uint32_t ub = (uint32_t)__bfloat16_as_ushort(__float2bfloat16_rn(b));
    return ua | (ub << 16);
}
// split float4 -> hi bf16x4 (uint2) + lo bf16x4 (uint2)
__device__ __forceinline__ void split4(float4 v, uint2& hi, uint2& lo) {
    __nv_bfloat16 hx = __float2bfloat16_rn(v.x), hy = __float2bfloat16_rn(v.y);
    __nv_bfloat16 hz = __float2bfloat16_rn(v.z), hw = __float2bfloat16_rn(v.w);
    hi.x = (uint32_t)__bfloat16_as_ushort(hx) | ((uint32_t)__bfloat16_as_ushort(hy) << 16);
    hi.y = (uint32_t)__bfloat16_as_ushort(hz) | ((uint32_t)__bfloat16_as_ushort(hw) << 16);
    lo.x = packbf2(v.x - __bfloat162float(hx), v.y - __bfloat162float(hy));
    lo.y = packbf2(v.z - __bfloat162float(hz), v.w - __bfloat162float(hw));
}

template<int KDIM, bool TRANSFORM>
__device__ __forceinline__ void hm_ldg(const float* __restrict__ A,
                                       const float* __restrict__ W,
                                       int c, float4* va, float4* vb, int tid) {
    const float* Ac = A + c * 32;
#pragma unroll
    for (int i = 0; i < 4; i++) {
        int s = tid + (i << 8);
        int row = s >> 3, kq = (s & 7) << 2;
        float4 v = *(const float4*)(Ac + (long)row * KDIM + kq);
        if (TRANSFORM) {
            int k = c * 32 + kq;
            float4 sc = *(const float4*)(g_scale + k);
            float4 sh = *(const float4*)(g_shift + k);
            v.x = fmaxf(fmaf(v.x, sc.x, sh.x), 0.f);
            v.y = fmaxf(fmaf(v.y, sc.y, sh.y), 0.f);
            v.z = fmaxf(fmaf(v.z, sc.z, sh.z), 0.f);
            v.w = fmaxf(fmaf(v.w, sc.w, sh.w), 0.f);
        }
        va[i] = v;
    }
    const float* Wc = W + c * 32;
#pragma unroll
    for (int i = 0; i < 8; i++) {
        int s = tid + (i << 8);
        int row = s >> 3, kq = (s & 7) << 2;
        vb[i] = *(const float4*)(Wc + (long)row * KDIM + kq);
    }
}

__device__ __forceinline__ void hm_sts(char* bp, const float4* va, const float4* vb, int tid) {
#pragma unroll
    for (int i = 0; i < 4; i++) {
        int s = tid + (i << 8);
        uint32_t off = (uint32_t)(s >> 3) * HROW + (uint32_t)(s & 7) * 8;
        uint2 hi, lo; split4(va[i], hi, lo);
        *(uint2*)(bp + off) = hi;
        *(uint2*)(bp + HA_SZ + off) = lo;
    }
#pragma unroll
    for (int i = 0; i < 8; i++) {
        int s = tid + (i << 8);
        uint32_t off = (uint32_t)(s >> 3) * HROW + (uint32_t)(s & 7) * 8;
        uint2 hi, lo; split4(vb[i], hi, lo);
        *(uint2*)(bp + 2 * HA_SZ + off) = hi;
        *(uint2*)(bp + 2 * HA_SZ + HB_SZ + off) = lo;
    }
}

template<int KDIM, bool TRANSFORM>
__global__ __launch_bounds__(256) void k_hmma(const float* __restrict__ A,
                                              const float* __restrict__ W,
                                              float* __restrict__ Y) {
    extern __shared__ char sm[];
    const int tid = threadIdx.x;
    const int wid = tid >> 5, lid = tid & 31;
    const int wm = wid >> 2, wn = wid & 3;   // 2 x 4 warp grid, warp tile 64x64
    const int NCH = KDIM / 32;
    const uint32_t sbase = smem_u32(sm);

    // per-lane ldmatrix offsets
    const uint32_t laneA = (uint32_t)(((lid & 7) + ((lid >> 3) & 1) * 8) * HROW + (lid >> 4) * 16);
    const uint32_t laneB = (uint32_t)(((lid & 7) + ((lid >> 4) & 1) * 8) * HROW + ((lid >> 3) & 1) * 16);

    A += (long)blockIdx.x * 128 * KDIM;

    float acc[4][8][4];
#pragma unroll
    for (int i = 0; i < 4; i++)
#pragma unroll
        for (int j = 0; j < 8; j++)
#pragma unroll
            for (int e = 0; e < 4; e++) acc[i][j][e] = 0.f;

    // prologue: chunk 0 -> buf 0
    {
        float4 va[4], vb[8];
        hm_ldg<KDIM, TRANSFORM>(A, W, 0, va, vb, tid);
        hm_sts(sm, va, vb, tid);
    }
    __syncthreads();

    for (int c = 0; c < NCH; c++) {
        float4 va[4], vb[8];
        if (c + 1 < NCH) hm_ldg<KDIM, TRANSFORM>(A, W, c + 1, va, vb, tid);

        const uint32_t base = sbase + (uint32_t)(c & 1) * HBUF;
#pragma unroll
        for (int ks = 0; ks < 2; ks++) {
            uint32_t aH[16], aL[16];
            const uint32_t a0 = base + (uint32_t)(wm * 64) * HROW + (uint32_t)ks * 32 + laneA;
#pragma unroll
            for (int mt = 0; mt < 4; mt++) ldsm4(aH + 4 * mt, a0 + (uint32_t)mt * (16 * HROW));
#pragma unroll
            for (int mt = 0; mt < 4; mt++) ldsm4(aL + 4 * mt, a0 + HA_SZ + (uint32_t)mt * (16 * HROW));
#pragma unroll
            for (int ng = 0; ng < 4; ng++) {
                const uint32_t b0 = base + 2 * HA_SZ +
                    (uint32_t)(wn * 64 + ng * 16) * HROW + (uint32_t)ks * 32 + laneB;
                uint32_t bh[4], bl[4];
                ldsm4(bh, b0);
                ldsm4(bl, b0 + HB_SZ);
#pragma unroll
                for (int mt = 0; mt < 4; mt++) {
                    float* C0 = acc[mt][2 * ng];
                    float* C1 = acc[mt][2 * ng + 1];
                    mma16816(C0, aH + 4 * mt, bh[0], bh[1]);
                    mma16816(C0, aH + 4 * mt, bl[0], bl[1]);
                    mma16816(C0, aL + 4 * mt, bh[0], bh[1]);
                    mma16816(C1, aH + 4 * mt, bh[2], bh[3]);
                    mma16816(C1, aH + 4 * mt, bl[2], bl[3]);
                    mma16816(C1, aL + 4 * mt, bh[2], bh[3]);
                }
            }
        }
        __syncthreads();
        if (c + 1 < NCH) {
            hm_sts(sm + (size_t)((c + 1) & 1) * HBUF, va, vb, tid);
            __syncthreads();
        }
    }

    // ---- epilogue: store Y + BN partials (deterministic order) ----
    const int g = lid >> 2, t = lid & 3;
    const int rowbase = blockIdx.x * 128 + wm * 64;
    const int colbase = wn * 64;
#pragma unroll
    for (int mt = 0; mt < 4; mt++) {
#pragma unroll
        for (int nt = 0; nt < 8; nt++) {
            float* c = acc[mt][nt];
            long r0 = (long)(rowbase + mt * 16 + g) * COUT + colbase + nt * 8 + 2 * t;
            *(float2*)&Y[r0] = make_float2(c[0], c[1]);
            *(float2*)&Y[r0 + 8 * COUT] = make_float2(c[2], c[3]);
        }
    }
    // per-warp channel sums over its 64 rows
    float* sm_s = (float*)sm;               // [2][256]
    float* sm_q = (float*)(sm + 2048);      // [2][256]
#pragma unroll
    for (int nt = 0; nt < 8; nt++) {
        float s0 = 0.f, s1 = 0.f, q0 = 0.f, q1 = 0.f;
#pragma unroll
        for (int mt = 0; mt < 4; mt++) {
            float* c = acc[mt][nt];
            s0 += c[0] + c[2];
            s1 += c[1] + c[3];
            q0 += c[0] * c[0] + c[2] * c[2];
            q1 += c[1] * c[1] + c[3] * c[3];
        }
#pragma unroll
        for (int m = 4; m <= 16; m <<= 1) {
            s0 += __shfl_xor_sync(0xffffffffu, s0, m);
            s1 += __shfl_xor_sync(0xffffffffu, s1, m);
            q0 += __shfl_xor_sync(0xffffffffu, q0, m);
            q1 += __shfl_xor_sync(0xffffffffu, q1, m);
        }
        if (g == 0) {
            int col = colbase + nt * 8 + 2 * t;
            sm_s[wm * 256 + col] = s0; sm_s[wm * 256 + col + 1] = s1;
            sm_q[wm * 256 + col] = q0; sm_q[wm * 256 + col + 1] = q1;
        }
    }
    __syncthreads();
    g_ps[blockIdx.x * COUT + tid] = sm_s[tid] + sm_s[256 + tid];
    g_pq[blockIdx.x * COUT + tid] = sm_q[tid] + sm_q[256 + tid];
}

// ---------------- BN finalize -------------------------------------------------
__global__ void k_bnfinal(const float* __restrict__ g, const float* __restrict__ bt) {
    int j = threadIdx.x;
    float s = 0.f, q = 0.f;
    for (int b = 0; b < 128; b++) { s += g_ps[b * COUT + j]; q += g_pq[b * COUT + j]; }
    float mean = s * (1.0f / NQ);
    float var = q * (1.0f / NQ) - mean * mean;
    float rstd = rsqrtf(var + BNEPS);
    float sc = g[j] * rstd;
    g_scale[j] = sc;
    g_shift[j] = bt[j] - mean * sc;
}

// final: out[o*N + n] = relu(norm(y2[n][o])) — transposing write via smem tile
__global__ void k_outtrans(const float* __restrict__ Y, float* __restrict__ out) {
    __shared__ float tile[32][33];
    int n0 = blockIdx.x * 32, o0 = blockIdx.y * 32;
    int tx = threadIdx.x, ty = threadIdx.y;
#pragma unroll
    for (int i = 0; i < 4; i++)
        tile[ty + 8 * i][tx] = Y[(long)(n0 + ty + 8 * i) * COUT + o0 + tx];
    __syncthreads();
#pragma unroll
    for (int i = 0; i < 4; i++) {
        int o = o0 + ty + 8 * i;
        float v = fmaf(tile[tx][ty + 8 * i], g_scale[o], g_shift[o]);
        out[(long)o * NQ + n0 + tx] = fmaxf(v, 0.f);
    }
}

// ---------------- launch ------------------------------------------------------
extern "C" void kernel_launch(void* const* d_in, const int* in_sizes, int n_in,
                              void* d_out, int out_size) {
    const float* xyz1 = (const float*)d_in[0];
    const float* xyz2 = (const float*)d_in[1];
    const int* pid1 = (const int*)d_in[2];
    const int* pid2 = (const int*)d_in[3];
    const float* points1 = (const float*)d_in[4];
    const float* points2 = (const float*)d_in[5];
    const float* w0 = (const float*)d_in[6];
    const float* gg0 = (const float*)d_in[8];
    const float* bt0 = (const float*)d_in[9];
    const float* w1 = (const float*)d_in[10];
    const float* gg1 = (const float*)d_in[12];
    const float* bt1 = (const float*)d_in[13];
    float* out = (float*)d_out;

    float *p_feats, *p_f2t, *p_y, *p_y2;
    cudaGetSymbolAddress((void**)&p_feats, g_feats);
    cudaGetSymbolAddress((void**)&p_f2t, g_f2t);
    cudaGetSymbolAddress((void**)&p_y, g_y);
    cudaGetSymbolAddress((void**)&p_y2, g_y2);

    cudaFuncSetAttribute(k_hmma<CIN, false>,
                         cudaFuncAttributeMaxDynamicSharedMemorySize, HSMEM);
    cudaFuncSetAttribute(k_hmma<COUT, true>,
                         cudaFuncAttributeMaxDynamicSharedMemorySize, HSMEM);

    k_init<<<1, 256>>>(pid1);
    k_count<<<NQ / 256, 256>>>(pid1, pid2);
    k_offsets<<<1, 1>>>();
    k_scatter<<<NQ / 256, 256>>>(xyz1, xyz2, pid1, pid2);

    // points1 [256][N] -> feats[n][c] (c<256); points2 [256][S] -> f2t[s][c]
    k_transpose<<<dim3(NQ / 32, 256 / 32), dim3(32, 8)>>>(points1, p_feats, NQ, CIN);
    k_transpose<<<dim3(NS / 32, 256 / 32), dim3(32, 8)>>>(points2, p_f2t, NS, D2C);

    k_knn<<<(NQ * 4) / 256, 256>>>();
    k_interp<<<(NQ * 32) / 256, 256>>>();

    // layer 1: 512 -> 256 (bf16x3 HMMA; bias cancels through BN; BN partials fused)
    k_hmma<CIN, false><<<NQ / 128, 256, HSMEM>>>(p_feats, w0, p_y);
    k_bnfinal<<<1, 256>>>(gg0, bt0);

    // layer 2: 256 -> 256 (BN+ReLU of layer1 fused into A-tile load)
    k_hmma<COUT, true><<<NQ / 128, 256, HSMEM>>>(p_y, w1, p_y2);
    k_bnfinal<<<1, 256>>>(gg1, bt1);
    k_outtrans<<<dim3(NQ / 32, COUT / 32), dim3(32, 8)>>>(p_y2, out);
}

// round 8
// speedup vs baseline: 1.9986x; 1.6425x over previous
#include <cuda_runtime.h>
#include <cuda_bf16.h>
#include <cstdint>

#define NQ 16384
#define NS 4096
#define NP 16
#define D2C 256
#define CIN 512
#define COUT 256
#define BIGD 1e8f
#define WEPS 1e-8f
#define BNEPS 1e-5f

// ---------------- scratch (static device globals; no allocation) -------------
__device__ __align__(16) __nv_bfloat16 g_fAh[NQ * CIN];  // feats hi plane [N][512]
__device__ __align__(16) __nv_bfloat16 g_fAl[NQ * CIN];  // feats lo plane
__device__ __align__(16) __nv_bfloat16 g_wh[CIN * COUT + COUT * COUT]; // w0|w1 hi
__device__ __align__(16) __nv_bfloat16 g_wl[CIN * COUT + COUT * COUT]; // w0|w1 lo
__device__ __align__(16) float g_f2t[NS * D2C];     // points2 transposed [S][256]
__device__ __align__(16) float g_y[NQ * COUT];      // pre-BN layer1
__device__ __align__(16) float g_y2[NQ * COUT];     // pre-BN layer2
__device__ int   g_kidx[NQ * 3];
__device__ float g_kw[NQ * 3];
__device__ __align__(16) float4 g_b2[NS];           // bucketed xyz2 (x,y,z,origIdx)
__device__ __align__(16) float4 g_b1[NQ];           // bucketed xyz1 (x,y,z,origN)
__device__ int g_qp[NQ];                            // piece id per bucketed query
__device__ int g_cnt1[NP], g_cnt2[NP], g_fill1[NP], g_fill2[NP];  // zeroed at graph end
__device__ float g_ps[128 * COUT], g_pq[128 * COUT]; // BN partials (per GEMM CTA)
__device__ float g_scale[COUT], g_shift[COUT];

// ---------------- helpers -----------------------------------------------------
__device__ __forceinline__ uint32_t smem_u32(const void* p) {
    uint32_t a;
    asm("{ .reg .u64 t; cvta.to.shared.u64 t, %1; cvt.u32.u64 %0, t; }" : "=r"(a) : "l"(p));
    return a;
}
__device__ __forceinline__ uint32_t packbf2(float a, float b) {
    uint32_t ua = (uint32_t)__bfloat16_as_ushort(__float2bfloat16_rn(a));
    uint32_t ub = (uint32_t)__bfloat16_as_ushort(__float2bfloat16_rn(b));
    return ua | (ub << 16);
}
__device__ __forceinline__ void split4(float4 v, uint2& hi, uint2& lo) {
    __nv_bfloat16 hx = __float2bfloat16_rn(v.x), hy = __float2bfloat16_rn(v.y);
    __nv_bfloat16 hz = __float2bfloat16_rn(v.z), hw = __float2bfloat16_rn(v.w);
    hi.x = (uint32_t)__bfloat16_as_ushort(hx) | ((uint32_t)__bfloat16_as_ushort(hy) << 16);
    hi.y = (uint32_t)__bfloat16_as_ushort(hz) | ((uint32_t)__bfloat16_as_ushort(hw) << 16);
    lo.x = packbf2(v.x - __bfloat162float(hx), v.y - __bfloat162float(hy));
    lo.y = packbf2(v.z - __bfloat162float(hz), v.w - __bfloat162float(hw));
}
// int64-vs-int32 piece-id detection, per block (barrier included)
__device__ __forceinline__ int detect_is64(const int* pid1w, int t) {
    int flag = (pid1w[2 * (t & 255) + 1] != 0);
    int any = __syncthreads_or(flag);
    return !any;
}

// ---------------- weight pre-split -------------------------------------------
__global__ void k_splitW(const float* __restrict__ w0, const float* __restrict__ w1) {
    int i = blockIdx.x * 256 + threadIdx.x;        // quad index; 49152 total
    float4 v = (i < 32768) ? ((const float4*)w0)[i] : ((const float4*)w1)[i - 32768];
    uint2 hi, lo; split4(v, hi, lo);
    *(uint2*)&g_wh[4 * i] = hi;
    *(uint2*)&g_wl[4 * i] = lo;
}

// ---------------- count (smem histogram) --------------------------------------
__global__ void k_count(const int* __restrict__ pid1w, const int* __restrict__ pid2w) {
    __shared__ int h1[NP], h2[NP];
    int t = threadIdx.x;
    if (t < NP) { h1[t] = 0; h2[t] = 0; }
    int is64 = detect_is64(pid1w, t);              // includes barrier
    int i = blockIdx.x * 256 + t;
    int p1 = is64 ? pid1w[2 * i] : pid1w[i];
    atomicAdd(&h1[p1], 1);
    if (i < NS) {
        int p2 = is64 ? pid2w[2 * i] : pid2w[i];
        atomicAdd(&h2[p2], 1);
    }
    __syncthreads();
    if (t < NP) {
        if (h1[t]) atomicAdd(&g_cnt1[t], h1[t]);
        if (h2[t]) atomicAdd(&g_cnt2[t], h2[t]);
    }
}

// ---------------- scatter (block ranges via one atomic per piece) -------------
__global__ void k_scatter(const float* __restrict__ x1, const float* __restrict__ x2,
                          const int* __restrict__ pid1w, const int* __restrict__ pid2w) {
    __shared__ int h1[NP], h2[NP], b1[NP], b2[NP], r1[NP], r2[NP];
    int t = threadIdx.x;
    if (t < NP) { h1[t] = 0; h2[t] = 0; r1[t] = 0; r2[t] = 0; }
    int is64 = detect_is64(pid1w, t);
    int i = blockIdx.x * 256 + t;
    int p1 = is64 ? pid1w[2 * i] : pid1w[i];
    atomicAdd(&h1[p1], 1);
    int p2 = -1;
    if (i < NS) {
        p2 = is64 ? pid2w[2 * i] : pid2w[i];
        atomicAdd(&h2[p2], 1);
    }
    __syncthreads();
    if (t < NP) {
        int o1 = 0, o2 = 0;
        for (int j = 0; j < t; j++) { o1 += g_cnt1[j]; o2 += g_cnt2[j]; }
        b1[t] = o1 + atomicAdd(&g_fill1[t], h1[t]);
        b2[t] = o2 + atomicAdd(&g_fill2[t], h2[t]);
    }
    __syncthreads();
    {
        int pos = b1[p1] + atomicAdd(&r1[p1], 1);
        g_b1[pos] = make_float4(x1[i], x1[NQ + i], x1[2 * NQ + i], __int_as_float(i));
        g_qp[pos] = p1;
    }
    if (i < NS) {
        int pos = b2[p2] + atomicAdd(&r2[p2], 1);
        g_b2[pos] = make_float4(x2[i], x2[NS + i], x2[2 * NS + i], __int_as_float(i));
    }
}

// ---------------- transposes ---------------------------------------------------
// points1 [256][N] -> feats planes [n][k<256] (bf16 hi/lo)
__global__ void k_tsplit(const float* __restrict__ src) {
    __shared__ float tile[32][33];
    int c0 = blockIdx.x * 32, r0 = blockIdx.y * 32;   // c0: n-base, r0: k-base
    int tx = threadIdx.x, ty = threadIdx.y;
#pragma unroll
    for (int i = 0; i < 4; i++)
        tile[ty + 8 * i][tx] = src[(r0 + ty + 8 * i) * NQ + c0 + tx];
    __syncthreads();
#pragma unroll
    for (int i = 0; i < 4; i++) {
        int n = c0 + ty + 8 * i, k = r0 + tx;
        float v = tile[tx][ty + 8 * i];
        __nv_bfloat16 h = __float2bfloat16_rn(v);
        g_fAh[(long)n * CIN + k] = h;
        g_fAl[(long)n * CIN + k] = __float2bfloat16_rn(v - __bfloat162float(h));
    }
}
// points2 [256][S] -> f2t [s][256] fp32
__global__ void k_transpose(const float* __restrict__ src, float* __restrict__ dst,
                            int Cc, int dstStride) {
    __shared__ float tile[32][33];
    int c0 = blockIdx.x * 32, r0 = blockIdx.y * 32;
    int tx = threadIdx.x, ty = threadIdx.y;
#pragma unroll
    for (int i = 0; i < 4; i++)
        tile[ty + 8 * i][tx] = src[(r0 + ty + 8 * i) * Cc + c0 + tx];
    __syncthreads();
#pragma unroll
    for (int i = 0; i < 4; i++)
        dst[(c0 + ty + 8 * i) * (long)dstStride + r0 + tx] = tile[tx][ty + 8 * i];
}

// ---------------- KNN (top-3 within same piece) ------------------------------
__device__ __forceinline__ void topk_ins(float d, int i,
                                         float& d0, float& d1, float& d2,
                                         int& i0, int& i1, int& i2) {
    if (d < d2) {
        if (d < d1) {
            d2 = d1; i2 = i1;
            if (d < d0) { d1 = d0; i1 = i0; d0 = d; i0 = i; }
            else        { d1 = d;  i1 = i; }
        } else { d2 = d; i2 = i; }
    }
}

__global__ void k_knn() {
    __shared__ int soff[NP + 1];
    if (threadIdx.x == 0) {
        int s = 0; soff[0] = 0;
        for (int p = 0; p < NP; p++) { s += g_cnt2[p]; soff[p + 1] = s; }
    }
    __syncthreads();
    int t = blockIdx.x * blockDim.x + threadIdx.x;
    int q = t >> 2;
    int l4 = t & 3;
    float4 Q = g_b1[q];
    int p = g_qp[q];
    int s0 = soff[p], s1 = soff[p + 1];
    const float FINF = __int_as_float(0x7f800000);
    float d0 = FINF, d1 = FINF, d2 = FINF;
    int i0 = 0, i1 = 0, i2 = 0;
    int j = s0 + l4;
    for (; j + 4 < s1; j += 8) {
        float4 T = g_b2[j];
        float4 U = g_b2[j + 4];
        float dx = Q.x - T.x, dy = Q.y - T.y, dz = Q.z - T.z;
        float d = fmaf(dx, dx, fmaf(dy, dy, dz * dz));
        float ex = Q.x - U.x, ey = Q.y - U.y, ez = Q.z - U.z;
        float e = fmaf(ex, ex, fmaf(ey, ey, ez * ez));
        topk_ins(d, __float_as_int(T.w), d0, d1, d2, i0, i1, i2);
        topk_ins(e, __float_as_int(U.w), d0, d1, d2, i0, i1, i2);
    }
    if (j < s1) {
        float4 T = g_b2[j];
        float dx = Q.x - T.x, dy = Q.y - T.y, dz = Q.z - T.z;
        float d = fmaf(dx, dx, fmaf(dy, dy, dz * dz));
        topk_ins(d, __float_as_int(T.w), d0, d1, d2, i0, i1, i2);
    }
#pragma unroll
    for (int m = 1; m <= 2; m <<= 1) {
        float e0 = __shfl_xor_sync(0xffffffffu, d0, m);
        float e1 = __shfl_xor_sync(0xffffffffu, d1, m);
        float e2 = __shfl_xor_sync(0xffffffffu, d2, m);
        int j0 = __shfl_xor_sync(0xffffffffu, i0, m);
        int j1 = __shfl_xor_sync(0xffffffffu, i1, m);
        int j2 = __shfl_xor_sync(0xffffffffu, i2, m);
        topk_ins(e0, j0, d0, d1, d2, i0, i1, i2);
        topk_ins(e1, j1, d0, d1, d2, i0, i1, i2);
        topk_ins(e2, j2, d0, d1, d2, i0, i1, i2);
    }
    if (l4 == 0) {
        int n = __float_as_int(Q.w);
        if (!(d0 < FINF)) { i0 = 0;  d0 = BIGD; }
        if (!(d1 < FINF)) { i1 = i0; d1 = BIGD; }
        if (!(d2 < FINF)) { i2 = i0; d2 = BIGD; }
        float w0 = 1.0f / (d0 + WEPS);
        float w1 = 1.0f / (d1 + WEPS);
        float w2 = 1.0f / (d2 + WEPS);
        float inv = 1.0f / (w0 + w1 + w2);
        g_kidx[n * 3 + 0] = i0; g_kidx[n * 3 + 1] = i1; g_kidx[n * 3 + 2] = i2;
        g_kw[n * 3 + 0] = w0 * inv; g_kw[n * 3 + 1] = w1 * inv; g_kw[n * 3 + 2] = w2 * inv;
    }
}

// ---------------- interpolation: writes bf16 hi/lo planes ---------------------
__global__ void k_interp() {
    int wi = (blockIdx.x * blockDim.x + threadIdx.x) >> 5;
    int lane = threadIdx.x & 31;
    if (wi >= NQ) return;
    int i0 = g_kidx[wi * 3 + 0], i1 = g_kidx[wi * 3 + 1], i2 = g_kidx[wi * 3 + 2];
    float w0 = g_kw[wi * 3 + 0], w1 = g_kw[wi * 3 + 1], w2 = g_kw[wi * 3 + 2];
    const float4* r0 = (const float4*)(g_f2t + (long)i0 * D2C);
    const float4* r1 = (const float4*)(g_f2t + (long)i1 * D2C);
    const float4* r2 = (const float4*)(g_f2t + (long)i2 * D2C);
    long ob = (long)wi * CIN + 256;
#pragma unroll
    for (int c = lane; c < D2C / 4; c += 32) {
        float4 a = r0[c], b = r1[c], cc = r2[c];
        float4 v;
        v.x = w0 * a.x + w1 * b.x + w2 * cc.x;
        v.y = w0 * a.y + w1 * b.y + w2 * cc.y;
        v.z = w0 * a.z + w1 * b.z + w2 * cc.z;
        v.w = w0 * a.w + w1 * b.w + w2 * cc.w;
        uint2 hi, lo; split4(v, hi, lo);
        *(uint2*)&g_fAh[ob + 4 * c] = hi;
        *(uint2*)&g_fAl[ob + 4 * c] = lo;
    }
}

// ============================================================================
// HMMA bf16x3 GEMM: C[i][j] = sum_k A[i][k]*B[j][k]  (TN, K-major, fp32 acc)
// CTA = 128M x 256N, K chunk 32, hi/lo bf16 planes, double buffered.
// MODE 0: A from pre-split planes (cp.async). MODE 1: A = fp32 y, BN+ReLU+split.
// B always from pre-split W planes via cp.async.
// ============================================================================
#define HROW 80
#define HA_SZ (128 * HROW)
#define HB_SZ (256 * HROW)
#define HBUF (2 * HA_SZ + 2 * HB_SZ)
#define HSMEM (2 * HBUF)

__device__ __forceinline__ void cp16(uint32_t dst, const void* src) {
    asm volatile("cp.async.ca.shared.global [%0], [%1], 16;" :: "r"(dst), "l"(src) : "memory");
}
__device__ __forceinline__ void ldsm4(uint32_t* r, uint32_t addr) {
    asm volatile("ldmatrix.sync.aligned.m8n8.x4.shared.b16 {%0,%1,%2,%3}, [%4];"
                 : "=r"(r[0]), "=r"(r[1]), "=r"(r[2]), "=r"(r[3]) : "r"(addr));
}
__device__ __forceinline__ void mma16816(float* c, const uint32_t* a, uint32_t b0, uint32_t b1) {
    asm volatile(
        "mma.sync.aligned.m16n8k16.row.col.f32.bf16.bf16.f32 "
        "{%0,%1,%2,%3}, {%4,%5,%6,%7}, {%8,%9}, {%0,%1,%2,%3};"
        : "+f"(c[0]), "+f"(c[1]), "+f"(c[2]), "+f"(c[3])
        : "r"(a[0]), "r"(a[1]), "r"(a[2]), "r"(a[3]), "r"(b0), "r"(b1));
}

template<int KDIM>
__device__ __forceinline__ void fill_B(const __nv_bfloat16* __restrict__ Wh,
                                       const __nv_bfloat16* __restrict__ Wl,
                                       int c, uint32_t sbuf, int tid) {
#pragma unroll
    for (int i = 0; i < 4; i++) {
        int idx = tid + (i << 8);
        int row = idx >> 2, seg = idx & 3;
        long go = (long)row * KDIM + c * 32 + seg * 8;
        uint32_t so = (uint32_t)row * HROW + (uint32_t)seg * 16;
        cp16(sbuf + 2 * HA_SZ + so, Wh + go);
        cp16(sbuf + 2 * HA_SZ + HB_SZ + so, Wl + go);
    }
}

template<int KDIM, int MODE>
__global__ __launch_bounds__(256) void k_hmma(const __nv_bfloat16* __restrict__ Ah,
                                              const __nv_bfloat16* __restrict__ Al,
                                              const float* __restrict__ Afp,
                                              const __nv_bfloat16* __restrict__ Wh,
                                              const __nv_bfloat16* __restrict__ Wl,
                                              float* __restrict__ Y) {
    extern __shared__ char sm[];
    const int tid = threadIdx.x;
    const int wid = tid >> 5, lid = tid & 31;
    const int wm = wid >> 2, wn = wid & 3;   // 2 x 4 warp grid, warp tile 64x64
    const int NCH = KDIM / 32;
    const uint32_t sbase = smem_u32(sm);

    const uint32_t laneA = (uint32_t)(((lid & 7) + ((lid >> 3) & 1) * 8) * HROW + (lid >> 4) * 16);
    const uint32_t laneB = (uint32_t)(((lid & 7) + ((lid >> 4) & 1) * 8) * HROW + ((lid >> 3) & 1) * 16);

    if (MODE == 0) { Ah += (long)blockIdx.x * 128 * KDIM; Al += (long)blockIdx.x * 128 * KDIM; }
    else           { Afp += (long)blockIdx.x * 128 * KDIM; }

    float acc[4][8][4];
#pragma unroll
    for (int i = 0; i < 4; i++)
#pragma unroll
        for (int jj = 0; jj < 8; jj++)
#pragma unroll
            for (int e = 0; e < 4; e++) acc[i][jj][e] = 0.f;

    // ---- fill lambda-ish via macro-expanded code ----
    auto fill = [&](int c, int buf) {
        uint32_t sbuf = sbase + (uint32_t)buf * HBUF;
        char* sbufp = sm + (size_t)buf * HBUF;
        if (MODE == 0) {
#pragma unroll
            for (int i = 0; i < 2; i++) {
                int idx = tid + (i << 8);
                int row = idx >> 2, seg = idx & 3;
                long go = (long)row * KDIM + c * 32 + seg * 8;
                uint32_t so = (uint32_t)row * HROW + (uint32_t)seg * 16;
                cp16(sbuf + so, Ah + go);
                cp16(sbuf + HA_SZ + so, Al + go);
            }
        } else {
#pragma unroll
            for (int i = 0; i < 4; i++) {
                int s = tid + (i << 8);
                int row = s >> 3, kq = (s & 7) << 2;
                float4 v = *(const float4*)(Afp + (long)row * KDIM + c * 32 + kq);
                int k = c * 32 + kq;
                float4 sc = *(const float4*)(g_scale + k);
                float4 sh = *(const float4*)(g_shift + k);
                v.x = fmaxf(fmaf(v.x, sc.x, sh.x), 0.f);
                v.y = fmaxf(fmaf(v.y, sc.y, sh.y), 0.f);
                v.z = fmaxf(fmaf(v.z, sc.z, sh.z), 0.f);
                v.w = fmaxf(fmaf(v.w, sc.w, sh.w), 0.f);
                uint2 hi, lo; split4(v, hi, lo);
                uint32_t so = (uint32_t)row * HROW + (uint32_t)kq * 2;
                *(uint2*)(sbufp + so) = hi;
                *(uint2*)(sbufp + HA_SZ + so) = lo;
            }
        }
        fill_B<KDIM>(Wh, Wl, c, sbuf, tid);
        asm volatile("cp.async.commit_group;" ::: "memory");
    };

    fill(0, 0);

    for (int c = 0; c < NCH; c++) {
        if (c + 1 < NCH) {
            fill(c + 1, (c + 1) & 1);
            asm volatile("cp.async.wait_group 1;" ::: "memory");
        } else {
            asm volatile("cp.async.wait_group 0;" ::: "memory");
        }
        __syncthreads();

        const uint32_t base = sbase + (uint32_t)(c & 1) * HBUF;
#pragma unroll
        for (int ks = 0; ks < 2; ks++) {
            uint32_t aH[16], aL[16];
            const uint32_t a0 = base + (uint32_t)(wm * 64) * HROW + (uint32_t)ks * 32 + laneA;
#pragma unroll
            for (int mt = 0; mt < 4; mt++) ldsm4(aH + 4 * mt, a0 + (uint32_t)mt * (16 * HROW));
#pragma unroll
            for (int mt = 0; mt < 4; mt++) ldsm4(aL + 4 * mt, a0 + HA_SZ + (uint32_t)mt * (16 * HROW));
#pragma unroll
            for (int ng = 0; ng < 4; ng++) {
                const uint32_t b0 = base + 2 * HA_SZ +
                    (uint32_t)(wn * 64 + ng * 16) * HROW + (uint32_t)ks * 32 + laneB;
                uint32_t bh[4], bl[4];
                ldsm4(bh, b0);
                ldsm4(bl, b0 + HB_SZ);
#pragma unroll
                for (int mt = 0; mt < 4; mt++) {
                    float* C0 = acc[mt][2 * ng];
                    float* C1 = acc[mt][2 * ng + 1];
                    mma16816(C0, aH + 4 * mt, bh[0], bh[1]);
                    mma16816(C0, aH + 4 * mt, bl[0], bl[1]);
                    mma16816(C0, aL + 4 * mt, bh[0], bh[1]);
                    mma16816(C1, aH + 4 * mt, bh[2], bh[3]);
                    mma16816(C1, aH + 4 * mt, bl[2], bl[3]);
                    mma16816(C1, aL + 4 * mt, bh[2], bh[3]);
                }
            }
        }
        __syncthreads();
    }

    // ---- epilogue: store Y + BN partials (deterministic order) ----
    const int g = lid >> 2, t = lid & 3;
    const int rowbase = blockIdx.x * 128 + wm * 64;
    const int colbase = wn * 64;
#pragma unroll
    for (int mt = 0; mt < 4; mt++) {
#pragma unroll
        for (int nt = 0; nt < 8; nt++) {
            float* c = acc[mt][nt];
            long r0 = (long)(rowbase + mt * 16 + g) * COUT + colbase + nt * 8 + 2 * t;
            *(float2*)&Y[r0] = make_float2(c[0], c[1]);
            *(float2*)&Y[r0 + 8 * COUT] = make_float2(c[2], c[3]);
        }
    }
    float* sm_s = (float*)sm;               // [2][256]
    float* sm_q = (float*)(sm + 2048);      // [2][256]
#pragma unroll
    for (int nt = 0; nt < 8; nt++) {
        float s0 = 0.f, s1 = 0.f, q0 = 0.f, q1 = 0.f;
#pragma unroll
        for (int mt = 0; mt < 4; mt++) {
            float* c = acc[mt][nt];
            s0 += c[0] + c[2];
            s1 += c[1] + c[3];
            q0 += c[0] * c[0] + c[2] * c[2];
            q1 += c[1] * c[1] + c[3] * c[3];
        }
#pragma unroll
        for (int m = 4; m <= 16; m <<= 1) {
            s0 += __shfl_xor_sync(0xffffffffu, s0, m);
            s1 += __shfl_xor_sync(0xffffffffu, s1, m);
            q0 += __shfl_xor_sync(0xffffffffu, q0, m);
            q1 += __shfl_xor_sync(0xffffffffu, q1, m);
        }
        if (g == 0) {
            int col = colbase + nt * 8 + 2 * t;
            sm_s[wm * 256 + col] = s0; sm_s[wm * 256 + col + 1] = s1;
            sm_q[wm * 256 + col] = q0; sm_q[wm * 256 + col + 1] = q1;
        }
    }
    __syncthreads();
    g_ps[blockIdx.x * COUT + tid] = sm_s[tid] + sm_s[256 + tid];
    g_pq[blockIdx.x * COUT + tid] = sm_q[tid] + sm_q[256 + tid];
}

// ---------------- BN finalize -------------------------------------------------
__global__ void k_bnfinal(const float* __restrict__ g, const float* __restrict__ bt) {
    int j = threadIdx.x;
    float s = 0.f, q = 0.f;
    for (int b = 0; b < 128; b++) { s += g_ps[b * COUT + j]; q += g_pq[b * COUT + j]; }
    float mean = s * (1.0f / NQ);
    float var = q * (1.0f / NQ) - mean * mean;
    float rstd = rsqrtf(var + BNEPS);
    float sc = g[j] * rstd;
    g_scale[j] = sc;
    g_shift[j] = bt[j] - mean * sc;
}

// final: out[o*N + n] = relu(norm(y2[n][o])); also re-zeroes bucket counters
__global__ void k_outtrans(const float* __restrict__ Y, float* __restrict__ out) {
    __shared__ float tile[32][33];
    int n0 = blockIdx.x * 32, o0 = blockIdx.y * 32;
    int tx = threadIdx.x, ty = threadIdx.y;
    if (blockIdx.x == 0 && blockIdx.y == 0 && ty == 0 && tx < NP) {
        g_cnt1[tx] = 0; g_cnt2[tx] = 0; g_fill1[tx] = 0; g_fill2[tx] = 0;
    }
#pragma unroll
    for (int i = 0; i < 4; i++)
        tile[ty + 8 * i][tx] = Y[(long)(n0 + ty + 8 * i) * COUT + o0 + tx];
    __syncthreads();
#pragma unroll
    for (int i = 0; i < 4; i++) {
        int o = o0 + ty + 8 * i;
        float v = fmaf(tile[tx][ty + 8 * i], g_scale[o], g_shift[o]);
        out[(long)o * NQ + n0 + tx] = fmaxf(v, 0.f);
    }
}

// ---------------- launch ------------------------------------------------------
extern "C" void kernel_launch(void* const* d_in, const int* in_sizes, int n_in,
                              void* d_out, int out_size) {
    const float* xyz1 = (const float*)d_in[0];
    const float* xyz2 = (const float*)d_in[1];
    const int* pid1 = (const int*)d_in[2];
    const int* pid2 = (const int*)d_in[3];
    const float* points1 = (const float*)d_in[4];
    const float* points2 = (const float*)d_in[5];
    const float* w0 = (const float*)d_in[6];
    const float* gg0 = (const float*)d_in[8];
    const float* bt0 = (const float*)d_in[9];
    const float* w1 = (const float*)d_in[10];
    const float* gg1 = (const float*)d_in[12];
    const float* bt1 = (const float*)d_in[13];
    float* out = (float*)d_out;

    __nv_bfloat16 *p_fAh, *p_fAl, *p_wh, *p_wl;
    float *p_f2t, *p_y, *p_y2;
    cudaGetSymbolAddress((void**)&p_fAh, g_fAh);
    cudaGetSymbolAddress((void**)&p_fAl, g_fAl);
    cudaGetSymbolAddress((void**)&p_wh, g_wh);
    cudaGetSymbolAddress((void**)&p_wl, g_wl);
    cudaGetSymbolAddress((void**)&p_f2t, g_f2t);
    cudaGetSymbolAddress((void**)&p_y, g_y);
    cudaGetSymbolAddress((void**)&p_y2, g_y2);

    cudaFuncSetAttribute((const void*)k_hmma<CIN, 0>,
                         cudaFuncAttributeMaxDynamicSharedMemorySize, HSMEM);
    cudaFuncSetAttribute((const void*)k_hmma<COUT, 1>,
                         cudaFuncAttributeMaxDynamicSharedMemorySize, HSMEM);

    k_splitW<<<192, 256>>>(w0, w1);
    k_tsplit<<<dim3(NQ / 32, 256 / 32), dim3(32, 8)>>>(points1);
    k_transpose<<<dim3(NS / 32, 256 / 32), dim3(32, 8)>>>(points2, p_f2t, NS, D2C);

    k_count<<<NQ / 256, 256>>>(pid1, pid2);
    k_scatter<<<NQ / 256, 256>>>(xyz1, xyz2, pid1, pid2);
    k_knn<<<(NQ * 4) / 256, 256>>>();
    k_interp<<<(NQ * 32) / 256, 256>>>();

    // layer 1: 512 -> 256 (pre-split bf16x3 planes; BN partials fused)
    k_hmma<CIN, 0><<<NQ / 128, 256, HSMEM>>>(p_fAh, p_fAl, nullptr, p_wh, p_wl, p_y);
    k_bnfinal<<<1, 256>>>(gg0, bt0);

    // layer 2: 256 -> 256 (BN+ReLU+split of layer1 fused into A-tile load)
    k_hmma<COUT, 1><<<NQ / 128, 256, HSMEM>>>(nullptr, nullptr, p_y,
                                              p_wh + CIN * COUT, p_wl + CIN * COUT, p_y2);
    k_bnfinal<<<1, 256>>>(gg1, bt1);
    k_outtrans<<<dim3(NQ / 32, COUT / 32), dim3(32, 8)>>>(p_y2, out);
}